// round 1
// baseline (speedup 1.0000x reference)
#include <cuda_runtime.h>
#include <cuda_bf16.h>

#define BB 2
#define NN 64
#define NGTK 8
#define CC 17
#define HWSZ 4096
#define S_TILES 8
#define TILE (HWSZ / S_TILES)   /* 512 */
#define TP2 (TILE / 2)          /* 256 float2-pairs per tile */

// Scratch (device globals — no runtime allocation allowed)
__device__ float2 g_pk[(size_t)BB * CC * NGTK * HWSZ];  // [b][c][g][hw] -> (c2, d2)
__device__ int    g_peak[BB * NGTK * CC];
__device__ float  g_valid[BB * NGTK * CC];
__device__ float  g_accm[BB * NN * NGTK];

// ---------------------------------------------------------------------------
__global__ void zero_acc_kernel() {
    int i = blockIdx.x * blockDim.x + threadIdx.x;
    if (i < BB * NN * NGTK) g_accm[i] = 0.0f;
}

// ---------------------------------------------------------------------------
// Per (b,g,c): validity, peak index, and packed (c2 = valid*(1-t)^4, d2 = t*c2)
__global__ void prep_kernel(const float* __restrict__ gt) {
    int bgc = blockIdx.x;   // = b*NGTK*CC + g*CC + c  (matches gt linearization)
    const float* src = gt + (size_t)bgc * HWSZ;

    float s = 0.0f;
    int pk = -1;
    for (int i = threadIdx.x; i < HWSZ; i += blockDim.x) {
        float t = src[i];
        s += t;
        if (t == 1.0f) pk = i;
    }
    for (int o = 16; o > 0; o >>= 1) {
        s += __shfl_xor_sync(0xffffffffu, s, o);
        pk = max(pk, __shfl_xor_sync(0xffffffffu, pk, o));
    }
    __shared__ float ws[8];
    __shared__ int   wp[8];
    __shared__ float s_valid;
    int w = threadIdx.x >> 5;
    if ((threadIdx.x & 31) == 0) { ws[w] = s; wp[w] = pk; }
    __syncthreads();
    if (threadIdx.x == 0) {
        float tot = 0.0f; int p = -1;
        int nw = blockDim.x >> 5;
        for (int i = 0; i < nw; i++) { tot += ws[i]; p = max(p, wp[i]); }
        s_valid = (tot != 0.0f) ? 1.0f : 0.0f;
        g_valid[bgc] = s_valid;
        g_peak[bgc]  = p;
    }
    __syncthreads();
    float v = s_valid;

    int c = bgc % CC;
    int g = (bgc / CC) % NGTK;
    int b = bgc / (CC * NGTK);
    float2* dst = g_pk + (size_t)((b * CC + c) * NGTK + g) * HWSZ;
    for (int i = threadIdx.x; i < HWSZ; i += blockDim.x) {
        float t  = src[i];
        float om = 1.0f - t;
        float w2 = om * om;
        float c2 = v * w2 * w2;     // exactly 0 at t==1
        dst[i] = make_float2(c2, t * c2);
    }
}

// ---------------------------------------------------------------------------
__device__ __forceinline__ void ph_pre(float x, float& A2, float& X2) {
    float e  = __expf(-fabsf(x));
    float r  = __fdividef(1.0f, 1.0f + e);
    float p  = (x >= 0.0f) ? r : e * r;             // sigmoid(x)
    float a  = fmaxf(x, 0.0f) + __logf(1.0f + e);   // softplus(x)
    float p2 = p * p;
    A2 = a * p2;
    X2 = x * p2;
}

// Dense focal-cost accumulation.
// grid = (S_TILES, CC, BB), 256 threads (8 warps).
// Warp w handles preds n = w*8 + rep*4 + u  (rep in 0..1, u in 0..3).
__global__ __launch_bounds__(256, 2) void dense_kernel(const float* __restrict__ ph) {
    int s = blockIdx.x, c = blockIdx.y, b = blockIdx.z;

    __shared__ float4 sg[NGTK][TP2];   // (c2,d2,c2,d2) per element pair — 32 KB
    {
        const float4* p4 = reinterpret_cast<const float4*>(g_pk);
#pragma unroll
        for (int g = 0; g < NGTK; ++g) {
            size_t f4 = ((size_t)((b * CC + c) * NGTK + g) * HWSZ + (size_t)s * TILE) >> 1;
            sg[g][threadIdx.x] = p4[f4 + threadIdx.x];
        }
    }
    __syncthreads();

    int w = threadIdx.x >> 5, L = threadIdx.x & 31;
    const float* phb = ph + ((size_t)b * NN * CC + c) * HWSZ + (size_t)s * TILE;

    for (int rep = 0; rep < 2; ++rep) {
        int n0 = w * 8 + rep * 4;
        float acc[4][NGTK];
#pragma unroll
        for (int u = 0; u < 4; u++)
#pragma unroll
            for (int g = 0; g < NGTK; g++) acc[u][g] = 0.0f;

#pragma unroll
        for (int i = 0; i < TP2 / 32; i++) {   // 8 iterations
            int ep = L + 32 * i;               // element-pair index
            float A2[4][2], X2[4][2];
#pragma unroll
            for (int u = 0; u < 4; u++) {
                float2 xv = *reinterpret_cast<const float2*>(
                    phb + (size_t)(n0 + u) * CC * HWSZ + 2 * ep);
                ph_pre(xv.x, A2[u][0], X2[u][0]);
                ph_pre(xv.y, A2[u][1], X2[u][1]);
            }
#pragma unroll
            for (int g = 0; g < NGTK; g++) {
                float4 ct = sg[g][ep];
#pragma unroll
                for (int u = 0; u < 4; u++) {
                    float t = acc[u][g];
                    t = fmaf(A2[u][0],  ct.x, t);
                    t = fmaf(-X2[u][0], ct.y, t);
                    t = fmaf(A2[u][1],  ct.z, t);
                    t = fmaf(-X2[u][1], ct.w, t);
                    acc[u][g] = t;
                }
            }
        }

        // butterfly warp reduction; lane (u*8+g) commits its value
#pragma unroll
        for (int u = 0; u < 4; u++) {
#pragma unroll
            for (int g = 0; g < NGTK; g++) {
                float v = acc[u][g];
                v += __shfl_xor_sync(0xffffffffu, v, 16);
                v += __shfl_xor_sync(0xffffffffu, v, 8);
                v += __shfl_xor_sync(0xffffffffu, v, 4);
                v += __shfl_xor_sync(0xffffffffu, v, 2);
                v += __shfl_xor_sync(0xffffffffu, v, 1);
                if (L == u * NGTK + g)
                    atomicAdd(&g_accm[(b * NN + n0 + u) * NGTK + g], v);
            }
        }
    }
}

// ---------------------------------------------------------------------------
__device__ __forceinline__ float fast_sigmoid(float x) {
    float e = __expf(-fabsf(x));
    float r = __fdividef(1.0f, 1.0f + e);
    return (x >= 0.0f) ? r : e * r;
}

// One block per (b,n). 160 threads: threads 0..135 cover (g,c).
__global__ void finalize_kernel(const float* __restrict__ ph,
                                const float* __restrict__ ps,
                                const float* __restrict__ po,
                                const float* __restrict__ go,
                                float* __restrict__ out) {
    int bn = blockIdx.x;
    int b = bn / NN;
    int t = threadIdx.x;

    __shared__ float pkacc[NGTK], offacc[NGTK], vcnt[NGTK], ssc;
    if (t < NGTK) { pkacc[t] = 0.0f; offacc[t] = 0.0f; vcnt[t] = 0.0f; }
    __syncthreads();

    if (t < NGTK * CC) {
        int g = t / CC, c = t % CC;
        int idx = (b * NGTK + g) * CC + c;
        float v = g_valid[idx];
        if (v > 0.0f) {
            // sparse peak correction: ce * (1-p)^2 at the single t==1 element
            int pk = g_peak[idx];
            float x = ph[((size_t)bn * CC + c) * HWSZ + pk];
            float e = __expf(-fabsf(x));
            float r = __fdividef(1.0f, 1.0f + e);
            float p = (x >= 0.0f) ? r : e * r;
            float a = fmaxf(x, 0.0f) + __logf(1.0f + e);
            float q = 1.0f - p;
            atomicAdd(&pkacc[g], (a - x) * q * q);
            // offset cost term
            float2 pov = *reinterpret_cast<const float2*>(po + ((size_t)bn * CC + c) * 2);
            float2 gov = *reinterpret_cast<const float2*>(go + (size_t)idx * 2);
            float s0 = fast_sigmoid(pov.x) - gov.x;
            float s1 = fast_sigmoid(pov.y) - gov.y;
            atomicAdd(&offacc[g], s0 * s0 + s1 * s1);
            atomicAdd(&vcnt[g], 1.0f);
        }
    }
    if (t == 0) {
        // score cost: ALPHA * bce(x,1) * (1-sigmoid(x))^2
        float x = ps[bn];
        float e = __expf(-fabsf(x));
        float r = __fdividef(1.0f, 1.0f + e);
        float sp = (x >= 0.0f) ? r : e * r;
        float bce1 = fmaxf(x, 0.0f) - x + __logf(1.0f + e);
        float q = 1.0f - sp;
        ssc = 0.25f * bce1 * q * q;
    }
    __syncthreads();

    if (t < NGTK) {
        float nk  = fmaxf(vcnt[t], 1.0f);
        float inv = __fdividef(1.0f, nk);
        float hms = (g_accm[bn * NGTK + t] + pkacc[t]) * inv;
        float off = offacc[t] * inv * 0.5f;
        out[bn * NGTK + t] = 2.0f * hms + ssc + off;   // HMS_W=2, SCORE_W=1, OFF_W=1
    }
}

// ---------------------------------------------------------------------------
extern "C" void kernel_launch(void* const* d_in, const int* in_sizes, int n_in,
                              void* d_out, int out_size) {
    const float *ph = nullptr, *gt = nullptr, *ps = nullptr, *po = nullptr, *go = nullptr;
    for (int i = 0; i < n_in; i++) {
        switch (in_sizes[i]) {
            case BB * NN * CC * HWSZ:   ph = (const float*)d_in[i]; break;  // 8,912,896
            case BB * NGTK * CC * HWSZ: gt = (const float*)d_in[i]; break;  // 1,114,112
            case BB * NN:               ps = (const float*)d_in[i]; break;  // 128
            case BB * NN * CC * 2:      po = (const float*)d_in[i]; break;  // 4,352
            case BB * NGTK * CC * 2:    go = (const float*)d_in[i]; break;  // 544
            default: break;
        }
    }
    float* out = (float*)d_out;

    zero_acc_kernel<<<(BB * NN * NGTK + 255) / 256, 256>>>();
    prep_kernel<<<BB * NGTK * CC, 256>>>(gt);
    dense_kernel<<<dim3(S_TILES, CC, BB), 256>>>(ph);
    finalize_kernel<<<BB * NN, 160>>>(ph, ps, po, go, out);
}